// round 7
// baseline (speedup 1.0000x reference)
#include <cuda_runtime.h>
#include <cuda_fp16.h>
#include <cstdint>
#include <cstddef>

// ---------------------------------------------------------------------------
// ContrastiveLoss: loss = mean_i( log(sum_j exp(cos(o_i,t_j))) - cos(o_i,t_i) )
// B = 16384, D = 256, fp32 in, fp32 scalar out.
//
// fp16 mma.sync pipeline with f16 ACCUMULATORS (testing 2x legacy HMMA rate).
//   prep:  normalize rows fp32 -> fp16; emits diag_i = <o_i,t_i> directly
//   main:  128x128x256 tiles, warp tile 32x32 (4x4 grid), two f16 acc sets
//          (k<128, k>=128) summed in fp32 at epilogue for precision. 1 wave.
//   final: deterministic reduction (128 logZ partials + 16384 diag terms)
// ---------------------------------------------------------------------------

#define NROW   16384
#define DDIM   256
#define NTILES 128
#define NCTA   128

static __device__ __align__(16) __half g_obf[NROW * DDIM];
static __device__ __align__(16) __half g_tbf[NROW * DDIM];
static __device__ float g_diag[NROW];
static __device__ float g_partials[NCTA];

// SMEM layout: A 64KB resident, B0/B1 64KB each, reduction scratch.
#define OFF_A    0
#define OFF_B0   65536
#define OFF_B1   131072
#define OFF_RED  196608   // 4 x 128 floats
#define OFF_DW   198656   // 4 floats
#define SMEM_DYN 198720

// ---------------------------------------------------------------------------
__device__ __forceinline__ uint32_t smem_u32(const void* p) {
    uint32_t a;
    asm("{ .reg .u64 t; cvta.to.shared.u64 t, %1; cvt.u32.u64 %0, t; }"
        : "=r"(a) : "l"(p));
    return a;
}
__device__ __forceinline__ void cp16(uint32_t dst, const void* src) {
    asm volatile("cp.async.cg.shared.global [%0], [%1], 16;" :: "r"(dst), "l"(src));
}
__device__ __forceinline__ void cp_commit() {
    asm volatile("cp.async.commit_group;" ::: "memory");
}
__device__ __forceinline__ void cp_wait0() {
    asm volatile("cp.async.wait_group 0;" ::: "memory");
}
__device__ __forceinline__ void ldm4(uint32_t* r, uint32_t addr) {
    asm volatile("ldmatrix.sync.aligned.m8n8.x4.shared.b16 {%0,%1,%2,%3}, [%4];"
                 : "=r"(r[0]), "=r"(r[1]), "=r"(r[2]), "=r"(r[3]) : "r"(addr));
}
// f16-accumulator MMA: D(16x8,f16) += A(16x16,f16) x B(16x8,f16)
__device__ __forceinline__ void mma16816_f16(uint32_t& d0, uint32_t& d1,
                                             const uint32_t* a,
                                             uint32_t b0, uint32_t b1) {
    asm volatile(
        "mma.sync.aligned.m16n8k16.row.col.f16.f16.f16.f16 "
        "{%0,%1}, {%2,%3,%4,%5}, {%6,%7}, {%0,%1};"
        : "+r"(d0), "+r"(d1)
        : "r"(a[0]), "r"(a[1]), "r"(a[2]), "r"(a[3]), "r"(b0), "r"(b1));
}

// Copy one 128x256 fp16 tile (64KB) into swizzled SMEM. 512 threads x 8 chunks.
__device__ __forceinline__ void tile_cp(const uint4* __restrict__ src,
                                        uint32_t dstbase, int tid) {
#pragma unroll
    for (int i = 0; i < 8; i++) {
        int c   = tid + (i << 9);
        int row = c >> 5, k16 = c & 31;
        cp16(dstbase + (row << 9) + ((k16 ^ (row & 7)) << 4), src + c);
    }
}

// ---------------------------------------------------------------------------
// Kernel 1: fp32 row norms -> normalized fp16, plus diag dot product.
// ---------------------------------------------------------------------------
__global__ void ContrastivePrep(const float* __restrict__ O,
                                const float* __restrict__ T) {
    __shared__ float red[12];
    int r = blockIdx.x, t = threadIdx.x;          // 128 threads, 2 elems each
    float2 a = ((const float2*)O)[(size_t)r * 128 + t];
    float2 b = ((const float2*)T)[(size_t)r * 128 + t];
    float so = a.x * a.x + a.y * a.y;
    float st = b.x * b.x + b.y * b.y;
#pragma unroll
    for (int s = 16; s; s >>= 1) {
        so += __shfl_xor_sync(0xffffffffu, so, s);
        st += __shfl_xor_sync(0xffffffffu, st, s);
    }
    if ((t & 31) == 0) { red[t >> 5] = so; red[4 + (t >> 5)] = st; }
    __syncthreads();
    float io = rsqrtf(red[0] + red[1] + red[2] + red[3]);
    float it = rsqrtf(red[4] + red[5] + red[6] + red[7]);
    __half2 oa = __floats2half2_rn(a.x * io, a.y * io);
    __half2 tb = __floats2half2_rn(b.x * it, b.y * it);
    ((__half2*)g_obf)[(size_t)r * 128 + t] = oa;
    ((__half2*)g_tbf)[(size_t)r * 128 + t] = tb;
    float dp = __half2float(oa.x) * __half2float(tb.x)
             + __half2float(oa.y) * __half2float(tb.y);
#pragma unroll
    for (int s = 16; s; s >>= 1) dp += __shfl_xor_sync(0xffffffffu, dp, s);
    if ((t & 31) == 0) red[8 + (t >> 5)] = dp;
    __syncthreads();
    if (t == 0) g_diag[r] = red[8] + red[9] + red[10] + red[11];
}

// ---------------------------------------------------------------------------
// Kernel 2: fused GEMM + exp rowsums. 128 CTAs x 512 threads (16 warps).
// Warp tile 32x32, warp grid 4x4. f16 accumulators, two sets per tile.
// ---------------------------------------------------------------------------
__global__ void __launch_bounds__(512, 1) ContrastiveMain() {
    extern __shared__ char smem[];
    const uint32_t sb = smem_u32(smem);
    const int tid  = threadIdx.x;
    const int lane = tid & 31, w = tid >> 5;
    const int wm = w >> 2, wn = w & 3;            // 4 x 4 warp grid
    const int g  = lane >> 2;
    const int cta = blockIdx.x;

    const int lrow = ((lane >> 3) & 1) * 8 + (lane & 7);
    const int lhi  = lane >> 4;
    const int x7   = lane & 7;

    uint32_t aoff[2], boff[2];
#pragma unroll
    for (int mf = 0; mf < 2; mf++)
        aoff[mf] = sb + OFF_A + (uint32_t)((wm * 32 + mf * 16 + lrow) << 9);
#pragma unroll
    for (int p = 0; p < 2; p++)
        boff[p] = (uint32_t)((wn * 32 + p * 16 + lrow) << 9);

    // Prologue: resident A + first B tile
    tile_cp((const uint4*)g_obf + (size_t)cta * 4096, sb + OFF_A, tid);
    tile_cp((const uint4*)g_tbf, sb + OFF_B0, tid);
    cp_commit();
    cp_wait0();
    __syncthreads();

    // Two f16 accumulator sets: dA for k-steps 0..7, dB for 8..15.
    uint32_t dA[2][4][2], dB[2][4][2];
#pragma unroll
    for (int mf = 0; mf < 2; mf++)
#pragma unroll
        for (int nf = 0; nf < 4; nf++)
#pragma unroll
            for (int r = 0; r < 2; r++) { dA[mf][nf][r] = 0u; dB[mf][nf][r] = 0u; }

    float sums[4];
#pragma unroll
    for (int s = 0; s < 4; s++) sums[s] = 0.f;

    for (int j = 0; j < NTILES; j++) {
        const uint32_t bbase = sb + ((j & 1) ? OFF_B1 : OFF_B0);
        if (j + 1 < NTILES) {
            tile_cp((const uint4*)g_tbf + (size_t)(j + 1) * 4096,
                    sb + ((j & 1) ? OFF_B0 : OFF_B1), tid);
            cp_commit();
        }

        // ---- K loop: 16 ksteps of k=16; set A for ks<8, set B for ks>=8 ----
#pragma unroll
        for (int ks = 0; ks < 16; ks++) {
            const uint32_t csel = (uint32_t)((((ks << 1) + lhi) ^ x7) << 4);
            uint32_t A2[2][4], Bm[2][4];
#pragma unroll
            for (int mf = 0; mf < 2; mf++) ldm4(A2[mf], aoff[mf] + csel);
#pragma unroll
            for (int p = 0; p < 2; p++)    ldm4(Bm[p], bbase + boff[p] + csel);
#pragma unroll
            for (int mf = 0; mf < 2; mf++)
#pragma unroll
                for (int p = 0; p < 2; p++) {
                    if (ks < 8) {
                        mma16816_f16(dA[mf][2*p][0],   dA[mf][2*p][1],
                                     A2[mf], Bm[p][0], Bm[p][2]);
                        mma16816_f16(dA[mf][2*p+1][0], dA[mf][2*p+1][1],
                                     A2[mf], Bm[p][1], Bm[p][3]);
                    } else {
                        mma16816_f16(dB[mf][2*p][0],   dB[mf][2*p][1],
                                     A2[mf], Bm[p][0], Bm[p][2]);
                        mma16816_f16(dB[mf][2*p+1][0], dB[mf][2*p+1][1],
                                     A2[mf], Bm[p][1], Bm[p][3]);
                    }
                }
        }

        // ---- epilogue: v = fA + fB (fp32), exp, accumulate per row-group ----
#pragma unroll
        for (int mf = 0; mf < 2; mf++)
#pragma unroll
            for (int h = 0; h < 2; h++) {          // h: acc reg = row group
                float acc = 0.f;
#pragma unroll
                for (int nf = 0; nf < 4; nf++) {
                    float2 fa = __half22float2(
                        *reinterpret_cast<__half2*>(&dA[mf][nf][h]));
                    float2 fb = __half22float2(
                        *reinterpret_cast<__half2*>(&dB[mf][nf][h]));
                    acc += __expf(fa.x + fb.x) + __expf(fa.y + fb.y);
                    dA[mf][nf][h] = 0u;
                    dB[mf][nf][h] = 0u;
                }
                sums[mf * 2 + h] += acc;
            }

        if (j + 1 < NTILES) cp_wait0();
        __syncthreads();
    }

    // ---- reductions (deterministic) ----
#pragma unroll
    for (int s = 0; s < 4; s++) {
        sums[s] += __shfl_xor_sync(0xffffffffu, sums[s], 1);
        sums[s] += __shfl_xor_sync(0xffffffffu, sums[s], 2);
    }
    float* rp = (float*)(smem + OFF_RED);   // [4][128]: per wn column-block
    float* dw = (float*)(smem + OFF_DW);    // [4]
    if ((lane & 3) == 0) {
#pragma unroll
        for (int s = 0; s < 4; s++) {
            int row = wm * 32 + (s >> 1) * 16 + (s & 1) * 8 + g;
            rp[wn * 128 + row] = sums[s];
        }
    }
    __syncthreads();
    if (tid < 128) {
        float srow = rp[tid] + rp[128 + tid] + rp[256 + tid] + rp[384 + tid];
        float li = __logf(srow);            // per-row log-sum-exp (max=0 safe)
#pragma unroll
        for (int off = 16; off; off >>= 1)
            li += __shfl_xor_sync(0xffffffffu, li, off);
        if (lane == 0) dw[w] = li;
    }
    __syncthreads();
    if (tid == 0) g_partials[cta] = dw[0] + dw[1] + dw[2] + dw[3];
}

// ---------------------------------------------------------------------------
// Kernel 3: deterministic final reduction: mean(logZ) - mean(diag)
// ---------------------------------------------------------------------------
__global__ void ContrastiveFinal(float* out) {
    __shared__ float red[256];
    int t = threadIdx.x;
    float s = 0.f;
    for (int i = t; i < NROW; i += 256) s -= g_diag[i];
    if (t < NCTA) s += g_partials[t];
    red[t] = s;
    __syncthreads();
#pragma unroll
    for (int k = 128; k; k >>= 1) {
        if (t < k) red[t] += red[t + k];
        __syncthreads();
    }
    if (t == 0) out[0] = red[0] / (float)NROW;
}

// ---------------------------------------------------------------------------
extern "C" void kernel_launch(void* const* d_in, const int* in_sizes, int n_in,
                              void* d_out, int out_size) {
    const float* O = (const float*)d_in[0];
    const float* T = (const float*)d_in[1];
    cudaFuncSetAttribute(ContrastiveMain,
                         cudaFuncAttributeMaxDynamicSharedMemorySize, SMEM_DYN);
    ContrastivePrep<<<NROW, 128>>>(O, T);
    ContrastiveMain<<<NCTA, 512, SMEM_DYN>>>();
    ContrastiveFinal<<<1, 256>>>((float*)d_out);
}

// round 8
// speedup vs baseline: 1.0756x; 1.0756x over previous
#include <cuda_runtime.h>
#include <cuda_bf16.h>
#include <cstdint>
#include <cstddef>

// ---------------------------------------------------------------------------
// ContrastiveLoss: loss = mean_i( log(sum_j exp(cos(o_i,t_j))) - cos(o_i,t_i) )
// B = 16384, D = 256, fp32 in, fp32 scalar out.
//
// bf16 mma.sync, 512 threads, warp tile 32x32 (4x4 grid), NT=128.
// Accumulator ping-pong: the exp/accumulate epilogue of tile j-1 is
// interleaved into the K-loop of tile j (2 elems per k-step), so MUFU
// issues under the tensor pipe instead of in a separate serial phase.
// ---------------------------------------------------------------------------

#define NROW   16384
#define DDIM   256
#define NTILES 128
#define NCTA   128

static __device__ __align__(16) __nv_bfloat16 g_obf[NROW * DDIM];
static __device__ __align__(16) __nv_bfloat16 g_tbf[NROW * DDIM];
static __device__ float g_diag[NROW];
static __device__ float g_partials[NCTA];

// SMEM layout: A 64KB resident, B0/B1 64KB each, reduction scratch.
#define OFF_A    0
#define OFF_B0   65536
#define OFF_B1   131072
#define OFF_RED  196608   // 4 x 128 floats
#define OFF_DW   198656   // 4 floats
#define SMEM_DYN 198720

// ---------------------------------------------------------------------------
__device__ __forceinline__ uint32_t smem_u32(const void* p) {
    uint32_t a;
    asm("{ .reg .u64 t; cvta.to.shared.u64 t, %1; cvt.u32.u64 %0, t; }"
        : "=r"(a) : "l"(p));
    return a;
}
__device__ __forceinline__ void cp16(uint32_t dst, const void* src) {
    asm volatile("cp.async.cg.shared.global [%0], [%1], 16;" :: "r"(dst), "l"(src));
}
__device__ __forceinline__ void cp_commit() {
    asm volatile("cp.async.commit_group;" ::: "memory");
}
__device__ __forceinline__ void cp_wait0() {
    asm volatile("cp.async.wait_group 0;" ::: "memory");
}
__device__ __forceinline__ void ldm4(uint32_t* r, uint32_t addr) {
    asm volatile("ldmatrix.sync.aligned.m8n8.x4.shared.b16 {%0,%1,%2,%3}, [%4];"
                 : "=r"(r[0]), "=r"(r[1]), "=r"(r[2]), "=r"(r[3]) : "r"(addr));
}
__device__ __forceinline__ void mma16816(float* d, const uint32_t* a,
                                         uint32_t b0, uint32_t b1) {
    asm volatile(
        "mma.sync.aligned.m16n8k16.row.col.f32.bf16.bf16.f32 "
        "{%0,%1,%2,%3}, {%4,%5,%6,%7}, {%8,%9}, {%0,%1,%2,%3};"
        : "+f"(d[0]), "+f"(d[1]), "+f"(d[2]), "+f"(d[3])
        : "r"(a[0]), "r"(a[1]), "r"(a[2]), "r"(a[3]), "r"(b0), "r"(b1));
}

// Copy one 128x256 bf16 tile (64KB) into swizzled SMEM. 512 threads x 8 chunks.
__device__ __forceinline__ void tile_cp(const uint4* __restrict__ src,
                                        uint32_t dstbase, int tid) {
#pragma unroll
    for (int i = 0; i < 8; i++) {
        int c   = tid + (i << 9);
        int row = c >> 5, k16 = c & 31;
        cp16(dstbase + (row << 9) + ((k16 ^ (row & 7)) << 4), src + c);
    }
}

// ---------------------------------------------------------------------------
// Kernel 1: fp32 row norms -> normalized bf16, plus diag dot product.
// ---------------------------------------------------------------------------
__global__ void ContrastivePrep(const float* __restrict__ O,
                                const float* __restrict__ T) {
    __shared__ float red[12];
    int r = blockIdx.x, t = threadIdx.x;          // 128 threads, 2 elems each
    float2 a = ((const float2*)O)[(size_t)r * 128 + t];
    float2 b = ((const float2*)T)[(size_t)r * 128 + t];
    float so = a.x * a.x + a.y * a.y;
    float st = b.x * b.x + b.y * b.y;
#pragma unroll
    for (int s = 16; s; s >>= 1) {
        so += __shfl_xor_sync(0xffffffffu, so, s);
        st += __shfl_xor_sync(0xffffffffu, st, s);
    }
    if ((t & 31) == 0) { red[t >> 5] = so; red[4 + (t >> 5)] = st; }
    __syncthreads();
    float io = rsqrtf(red[0] + red[1] + red[2] + red[3]);
    float it = rsqrtf(red[4] + red[5] + red[6] + red[7]);
    __nv_bfloat162 oa = __floats2bfloat162_rn(a.x * io, a.y * io);
    __nv_bfloat162 tb = __floats2bfloat162_rn(b.x * it, b.y * it);
    ((__nv_bfloat162*)g_obf)[(size_t)r * 128 + t] = oa;
    ((__nv_bfloat162*)g_tbf)[(size_t)r * 128 + t] = tb;
    float dp = __bfloat162float(oa.x) * __bfloat162float(tb.x)
             + __bfloat162float(oa.y) * __bfloat162float(tb.y);
#pragma unroll
    for (int s = 16; s; s >>= 1) dp += __shfl_xor_sync(0xffffffffu, dp, s);
    if ((t & 31) == 0) red[8 + (t >> 5)] = dp;
    __syncthreads();
    if (t == 0) g_diag[r] = red[8] + red[9] + red[10] + red[11];
}

// ---------------------------------------------------------------------------
// Kernel 2: fused GEMM + exp rowsums. 128 CTAs x 512 threads (16 warps).
// Warp tile 32x32, warp grid 4x4. Double accumulator sets d0/d1.
// ---------------------------------------------------------------------------

// DC: accumulating set (this tile). DE: set being epilogued (previous tile).
// Interleave 2 exp-elements of DE per k-step (32 elements over 16 k-steps).
#define TILE_BODY(DC, DE, BOFFS, EPI)                                         \
    do {                                                                      \
        const uint32_t bbase_ = sb + (BOFFS);                                 \
        _Pragma("unroll")                                                     \
        for (int ks = 0; ks < 16; ks++) {                                     \
            const uint32_t csel = (uint32_t)((((ks << 1) + lhi) ^ x7) << 4);  \
            uint32_t A2[2][4], Bm[2][4];                                      \
            _Pragma("unroll")                                                 \
            for (int mf = 0; mf < 2; mf++) ldm4(A2[mf], aoff[mf] + csel);     \
            _Pragma("unroll")                                                 \
            for (int p = 0; p < 2; p++)    ldm4(Bm[p], bbase_ + boff[p] + csel); \
            _Pragma("unroll")                                                 \
            for (int mf = 0; mf < 2; mf++)                                    \
                _Pragma("unroll")                                             \
                for (int p = 0; p < 2; p++) {                                 \
                    mma16816(DC[mf][2 * p],     A2[mf], Bm[p][0], Bm[p][2]);  \
                    mma16816(DC[mf][2 * p + 1], A2[mf], Bm[p][1], Bm[p][3]);  \
                }                                                             \
            if (EPI) {                                                        \
                _Pragma("unroll")                                             \
                for (int i = 0; i < 2; i++) {                                 \
                    const int e  = 2 * ks + i;                                \
                    const int mf = e >> 4, nf = (e >> 2) & 3, r = e & 3;      \
                    float v = DE[mf][nf][r];                                  \
                    DE[mf][nf][r] = 0.f;                                      \
                    sums[mf * 2 + (r >> 1)] += __expf(v);                     \
                }                                                             \
            }                                                                 \
        }                                                                     \
    } while (0)

__global__ void __launch_bounds__(512, 1) ContrastiveMain() {
    extern __shared__ char smem[];
    const uint32_t sb = smem_u32(smem);
    const int tid  = threadIdx.x;
    const int lane = tid & 31, w = tid >> 5;
    const int wm = w >> 2, wn = w & 3;            // 4 x 4 warp grid
    const int g  = lane >> 2;
    const int cta = blockIdx.x;

    const int lrow = ((lane >> 3) & 1) * 8 + (lane & 7);
    const int lhi  = lane >> 4;
    const int x7   = lane & 7;

    uint32_t aoff[2], boff[2];
#pragma unroll
    for (int mf = 0; mf < 2; mf++)
        aoff[mf] = sb + OFF_A + (uint32_t)((wm * 32 + mf * 16 + lrow) << 9);
#pragma unroll
    for (int p = 0; p < 2; p++)
        boff[p] = (uint32_t)((wn * 32 + p * 16 + lrow) << 9);

    // Prologue: resident A + B(0)
    tile_cp((const uint4*)g_obf + (size_t)cta * 4096, sb + OFF_A, tid);
    tile_cp((const uint4*)g_tbf, sb + OFF_B0, tid);
    cp_commit();
    cp_wait0();
    __syncthreads();

    float d0[2][4][4], d1[2][4][4];
#pragma unroll
    for (int mf = 0; mf < 2; mf++)
#pragma unroll
        for (int nf = 0; nf < 4; nf++)
#pragma unroll
            for (int r = 0; r < 4; r++) { d0[mf][nf][r] = 0.f; d1[mf][nf][r] = 0.f; }

    float sums[4];
#pragma unroll
    for (int s = 0; s < 4; s++) sums[s] = 0.f;

    // Tile 0 (set d0, no epilogue); prefetch B(1)
    tile_cp((const uint4*)g_tbf + 4096, sb + OFF_B1, tid);
    cp_commit();
    TILE_BODY(d0, d1, OFF_B0, false);
    cp_wait0();
    __syncthreads();

    // Tiles 1..126 in pairs (63 pairs)
    for (int jp = 0; jp < 63; jp++) {
        // tile 2jp+1 (set d1 from B1, epi d0); prefetch B(2jp+2) -> B0
        tile_cp((const uint4*)g_tbf + (size_t)(2 * jp + 2) * 4096,
                sb + OFF_B0, tid);
        cp_commit();
        TILE_BODY(d1, d0, OFF_B1, true);
        cp_wait0();
        __syncthreads();
        // tile 2jp+2 (set d0 from B0, epi d1); prefetch B(2jp+3) -> B1
        tile_cp((const uint4*)g_tbf + (size_t)(2 * jp + 3) * 4096,
                sb + OFF_B1, tid);
        cp_commit();
        TILE_BODY(d0, d1, OFF_B0, true);
        cp_wait0();
        __syncthreads();
    }

    // Tile 127 (set d1 from B1, epi d0), then tail epilogue of d1
    TILE_BODY(d1, d0, OFF_B1, true);
#pragma unroll
    for (int e = 0; e < 32; e++) {
        const int mf = e >> 4, nf = (e >> 2) & 3, r = e & 3;
        sums[mf * 2 + (r >> 1)] += __expf(d1[mf][nf][r]);
    }

    // ---- reductions (deterministic) ----
#pragma unroll
    for (int s = 0; s < 4; s++) {
        sums[s] += __shfl_xor_sync(0xffffffffu, sums[s], 1);
        sums[s] += __shfl_xor_sync(0xffffffffu, sums[s], 2);
    }
    float* rp = (float*)(smem + OFF_RED);   // [4][128]: per wn column-block
    float* dw = (float*)(smem + OFF_DW);    // [4]
    if ((lane & 3) == 0) {
#pragma unroll
        for (int s = 0; s < 4; s++) {
            int row = wm * 32 + (s >> 1) * 16 + (s & 1) * 8 + g;
            rp[wn * 128 + row] = sums[s];
        }
    }
    __syncthreads();
    if (tid < 128) {
        float srow = rp[tid] + rp[128 + tid] + rp[256 + tid] + rp[384 + tid];
        float li = __logf(srow);            // per-row log-sum-exp (max=0 safe)
#pragma unroll
        for (int off = 16; off; off >>= 1)
            li += __shfl_xor_sync(0xffffffffu, li, off);
        if (lane == 0) dw[w] = li;
    }
    __syncthreads();
    if (tid == 0) g_partials[cta] = dw[0] + dw[1] + dw[2] + dw[3];
}

// ---------------------------------------------------------------------------
// Kernel 3: deterministic final reduction: mean(logZ) - mean(diag)
// ---------------------------------------------------------------------------
__global__ void ContrastiveFinal(float* out) {
    __shared__ float red[256];
    int t = threadIdx.x;
    float s = 0.f;
    for (int i = t; i < NROW; i += 256) s -= g_diag[i];
    if (t < NCTA) s += g_partials[t];
    red[t] = s;
    __syncthreads();
#pragma unroll
    for (int k = 128; k; k >>= 1) {
        if (t < k) red[t] += red[t + k];
        __syncthreads();
    }
    if (t == 0) out[0] = red[0] / (float)NROW;
}

// ---------------------------------------------------------------------------
extern "C" void kernel_launch(void* const* d_in, const int* in_sizes, int n_in,
                              void* d_out, int out_size) {
    const float* O = (const float*)d_in[0];
    const float* T = (const float*)d_in[1];
    cudaFuncSetAttribute(ContrastiveMain,
                         cudaFuncAttributeMaxDynamicSharedMemorySize, SMEM_DYN);
    ContrastivePrep<<<NROW, 128>>>(O, T);
    ContrastiveMain<<<NCTA, 512, SMEM_DYN>>>();
    ContrastiveFinal<<<1, 256>>>((float*)d_out);
}

// round 10
// speedup vs baseline: 1.0882x; 1.0116x over previous
#include <cuda_runtime.h>
#include <cuda_bf16.h>
#include <cstdint>
#include <cstddef>

// ---------------------------------------------------------------------------
// ContrastiveLoss: loss = mean_i( log(sum_j exp(cos(o_i,t_j))) - cos(o_i,t_i) )
// B = 16384, D = 256, fp32 in, fp32 scalar out.
//
// bf16 mma.sync, 512 threads, warp tile 32x32 (4x4 grid), NT=128.
// Accumulator ping-pong: the exp/accumulate epilogue of tile j-1 is
// interleaved into the K-loop of tile j (2 elems per k-step), so MUFU
// issues under the tensor pipe instead of in a separate serial phase.
// Prep/final overhead minimized: warp-per-row prep (no barriers), wide final.
// (Resubmission of R9 — previous run died to a container/infra failure.)
// ---------------------------------------------------------------------------

#define NROW   16384
#define DDIM   256
#define NTILES 128
#define NCTA   128

static __device__ __align__(16) __nv_bfloat16 g_obf[NROW * DDIM];
static __device__ __align__(16) __nv_bfloat16 g_tbf[NROW * DDIM];
static __device__ float g_diag[NROW];
static __device__ float g_partials[NCTA];

// SMEM layout: A 64KB resident, B0/B1 64KB each, reduction scratch.
#define OFF_A    0
#define OFF_B0   65536
#define OFF_B1   131072
#define OFF_RED  196608   // 4 x 128 floats
#define OFF_DW   198656   // 4 floats
#define SMEM_DYN 198720

// ---------------------------------------------------------------------------
__device__ __forceinline__ uint32_t smem_u32(const void* p) {
    uint32_t a;
    asm("{ .reg .u64 t; cvta.to.shared.u64 t, %1; cvt.u32.u64 %0, t; }"
        : "=r"(a) : "l"(p));
    return a;
}
__device__ __forceinline__ void cp16(uint32_t dst, const void* src) {
    asm volatile("cp.async.cg.shared.global [%0], [%1], 16;" :: "r"(dst), "l"(src));
}
__device__ __forceinline__ void cp_commit() {
    asm volatile("cp.async.commit_group;" ::: "memory");
}
__device__ __forceinline__ void cp_wait0() {
    asm volatile("cp.async.wait_group 0;" ::: "memory");
}
__device__ __forceinline__ void ldm4(uint32_t* r, uint32_t addr) {
    asm volatile("ldmatrix.sync.aligned.m8n8.x4.shared.b16 {%0,%1,%2,%3}, [%4];"
                 : "=r"(r[0]), "=r"(r[1]), "=r"(r[2]), "=r"(r[3]) : "r"(addr));
}
__device__ __forceinline__ void mma16816(float* d, const uint32_t* a,
                                         uint32_t b0, uint32_t b1) {
    asm volatile(
        "mma.sync.aligned.m16n8k16.row.col.f32.bf16.bf16.f32 "
        "{%0,%1,%2,%3}, {%4,%5,%6,%7}, {%8,%9}, {%0,%1,%2,%3};"
        : "+f"(d[0]), "+f"(d[1]), "+f"(d[2]), "+f"(d[3])
        : "r"(a[0]), "r"(a[1]), "r"(a[2]), "r"(a[3]), "r"(b0), "r"(b1));
}

// Copy one 128x256 bf16 tile (64KB) into swizzled SMEM. 512 threads x 8 chunks.
__device__ __forceinline__ void tile_cp(const uint4* __restrict__ src,
                                        uint32_t dstbase, int tid) {
#pragma unroll
    for (int i = 0; i < 8; i++) {
        int c   = tid + (i << 9);
        int row = c >> 5, k16 = c & 31;
        cp16(dstbase + (row << 9) + ((k16 ^ (row & 7)) << 4), src + c);
    }
}

// ---------------------------------------------------------------------------
// Kernel 1: warp-per-row prep. Lane l owns elems [8l, 8l+8) of row r.
// No shared memory, no block barriers; pure shfl reductions.
// Grid 2048 x 256 threads (8 warps = 8 rows per block).
// ---------------------------------------------------------------------------
__global__ void __launch_bounds__(256) ContrastivePrep(
        const float* __restrict__ O, const float* __restrict__ T) {
    const int r    = blockIdx.x * 8 + (threadIdx.x >> 5);
    const int lane = threadIdx.x & 31;

    const float4* o4 = (const float4*)(O + (size_t)r * DDIM) + lane * 2;
    const float4* t4 = (const float4*)(T + (size_t)r * DDIM) + lane * 2;
    float4 a0 = o4[0], a1 = o4[1];
    float4 b0 = t4[0], b1 = t4[1];

    float so = a0.x*a0.x + a0.y*a0.y + a0.z*a0.z + a0.w*a0.w
             + a1.x*a1.x + a1.y*a1.y + a1.z*a1.z + a1.w*a1.w;
    float st = b0.x*b0.x + b0.y*b0.y + b0.z*b0.z + b0.w*b0.w
             + b1.x*b1.x + b1.y*b1.y + b1.z*b1.z + b1.w*b1.w;
#pragma unroll
    for (int s = 16; s; s >>= 1) {
        so += __shfl_xor_sync(0xffffffffu, so, s);
        st += __shfl_xor_sync(0xffffffffu, st, s);
    }
    const float io = rsqrtf(so), it = rsqrtf(st);

    __nv_bfloat162 oc[4], tc[4];
    oc[0] = __floats2bfloat162_rn(a0.x * io, a0.y * io);
    oc[1] = __floats2bfloat162_rn(a0.z * io, a0.w * io);
    oc[2] = __floats2bfloat162_rn(a1.x * io, a1.y * io);
    oc[3] = __floats2bfloat162_rn(a1.z * io, a1.w * io);
    tc[0] = __floats2bfloat162_rn(b0.x * it, b0.y * it);
    tc[1] = __floats2bfloat162_rn(b0.z * it, b0.w * it);
    tc[2] = __floats2bfloat162_rn(b1.x * it, b1.y * it);
    tc[3] = __floats2bfloat162_rn(b1.z * it, b1.w * it);
    ((uint4*)g_obf)[(size_t)r * 32 + lane] = *(uint4*)oc;
    ((uint4*)g_tbf)[(size_t)r * 32 + lane] = *(uint4*)tc;

    // diag_i from the bf16-rounded values (matches GEMM products)
    float dp = 0.f;
#pragma unroll
    for (int q = 0; q < 4; q++) {
        dp += __bfloat162float(oc[q].x) * __bfloat162float(tc[q].x)
            + __bfloat162float(oc[q].y) * __bfloat162float(tc[q].y);
    }
#pragma unroll
    for (int s = 16; s; s >>= 1) dp += __shfl_xor_sync(0xffffffffu, dp, s);
    if (lane == 0) g_diag[r] = dp;
}

// ---------------------------------------------------------------------------
// Kernel 2: fused GEMM + exp rowsums. 128 CTAs x 512 threads (16 warps).
// Warp tile 32x32, warp grid 4x4. Double accumulator sets d0/d1.
// ---------------------------------------------------------------------------

// DC: accumulating set (this tile). DE: set being epilogued (previous tile).
// Interleave 2 exp-elements of DE per k-step (32 elements over 16 k-steps).
#define TILE_BODY(DC, DE, BOFFS, EPI)                                         \
    do {                                                                      \
        const uint32_t bbase_ = sb + (BOFFS);                                 \
        _Pragma("unroll")                                                     \
        for (int ks = 0; ks < 16; ks++) {                                     \
            const uint32_t csel = (uint32_t)((((ks << 1) + lhi) ^ x7) << 4);  \
            uint32_t A2[2][4], Bm[2][4];                                      \
            _Pragma("unroll")                                                 \
            for (int mf = 0; mf < 2; mf++) ldm4(A2[mf], aoff[mf] + csel);     \
            _Pragma("unroll")                                                 \
            for (int p = 0; p < 2; p++)    ldm4(Bm[p], bbase_ + boff[p] + csel); \
            _Pragma("unroll")                                                 \
            for (int mf = 0; mf < 2; mf++)                                    \
                _Pragma("unroll")                                             \
                for (int p = 0; p < 2; p++) {                                 \
                    mma16816(DC[mf][2 * p],     A2[mf], Bm[p][0], Bm[p][2]);  \
                    mma16816(DC[mf][2 * p + 1], A2[mf], Bm[p][1], Bm[p][3]);  \
                }                                                             \
            if (EPI) {                                                        \
                _Pragma("unroll")                                             \
                for (int i = 0; i < 2; i++) {                                 \
                    const int e  = 2 * ks + i;                                \
                    const int mf = e >> 4, nf = (e >> 2) & 3, r = e & 3;      \
                    float v = DE[mf][nf][r];                                  \
                    DE[mf][nf][r] = 0.f;                                      \
                    sums[mf * 2 + (r >> 1)] += __expf(v);                     \
                }                                                             \
            }                                                                 \
        }                                                                     \
    } while (0)

__global__ void __launch_bounds__(512, 1) ContrastiveMain() {
    extern __shared__ char smem[];
    const uint32_t sb = smem_u32(smem);
    const int tid  = threadIdx.x;
    const int lane = tid & 31, w = tid >> 5;
    const int wm = w >> 2, wn = w & 3;            // 4 x 4 warp grid
    const int g  = lane >> 2;
    const int cta = blockIdx.x;

    const int lrow = ((lane >> 3) & 1) * 8 + (lane & 7);
    const int lhi  = lane >> 4;
    const int x7   = lane & 7;

    uint32_t aoff[2], boff[2];
#pragma unroll
    for (int mf = 0; mf < 2; mf++)
        aoff[mf] = sb + OFF_A + (uint32_t)((wm * 32 + mf * 16 + lrow) << 9);
#pragma unroll
    for (int p = 0; p < 2; p++)
        boff[p] = (uint32_t)((wn * 32 + p * 16 + lrow) << 9);

    // Prologue: resident A + B(0)
    tile_cp((const uint4*)g_obf + (size_t)cta * 4096, sb + OFF_A, tid);
    tile_cp((const uint4*)g_tbf, sb + OFF_B0, tid);
    cp_commit();
    cp_wait0();
    __syncthreads();

    float d0[2][4][4], d1[2][4][4];
#pragma unroll
    for (int mf = 0; mf < 2; mf++)
#pragma unroll
        for (int nf = 0; nf < 4; nf++)
#pragma unroll
            for (int r = 0; r < 4; r++) { d0[mf][nf][r] = 0.f; d1[mf][nf][r] = 0.f; }

    float sums[4];
#pragma unroll
    for (int s = 0; s < 4; s++) sums[s] = 0.f;

    // Tile 0 (set d0, no epilogue); prefetch B(1)
    tile_cp((const uint4*)g_tbf + 4096, sb + OFF_B1, tid);
    cp_commit();
    TILE_BODY(d0, d1, OFF_B0, false);
    cp_wait0();
    __syncthreads();

    // Tiles 1..126 in pairs (63 pairs)
    for (int jp = 0; jp < 63; jp++) {
        // tile 2jp+1 (set d1 from B1, epi d0); prefetch B(2jp+2) -> B0
        tile_cp((const uint4*)g_tbf + (size_t)(2 * jp + 2) * 4096,
                sb + OFF_B0, tid);
        cp_commit();
        TILE_BODY(d1, d0, OFF_B1, true);
        cp_wait0();
        __syncthreads();
        // tile 2jp+2 (set d0 from B0, epi d1); prefetch B(2jp+3) -> B1
        tile_cp((const uint4*)g_tbf + (size_t)(2 * jp + 3) * 4096,
                sb + OFF_B1, tid);
        cp_commit();
        TILE_BODY(d0, d1, OFF_B0, true);
        cp_wait0();
        __syncthreads();
    }

    // Tile 127 (set d1 from B1, epi d0), then tail epilogue of d1
    TILE_BODY(d1, d0, OFF_B1, true);
#pragma unroll
    for (int e = 0; e < 32; e++) {
        const int mf = e >> 4, nf = (e >> 2) & 3, r = e & 3;
        sums[mf * 2 + (r >> 1)] += __expf(d1[mf][nf][r]);
    }

    // ---- reductions (deterministic) ----
#pragma unroll
    for (int s = 0; s < 4; s++) {
        sums[s] += __shfl_xor_sync(0xffffffffu, sums[s], 1);
        sums[s] += __shfl_xor_sync(0xffffffffu, sums[s], 2);
    }
    float* rp = (float*)(smem + OFF_RED);   // [4][128]: per wn column-block
    float* dw = (float*)(smem + OFF_DW);    // [4]
    if ((lane & 3) == 0) {
#pragma unroll
        for (int s = 0; s < 4; s++) {
            int row = wm * 32 + (s >> 1) * 16 + (s & 1) * 8 + g;
            rp[wn * 128 + row] = sums[s];
        }
    }
    __syncthreads();
    if (tid < 128) {
        float srow = rp[tid] + rp[128 + tid] + rp[256 + tid] + rp[384 + tid];
        float li = __logf(srow);            // per-row log-sum-exp (max=0 safe)
#pragma unroll
        for (int off = 16; off; off >>= 1)
            li += __shfl_xor_sync(0xffffffffu, li, off);
        if (lane == 0) dw[w] = li;
    }
    __syncthreads();
    if (tid == 0) g_partials[cta] = dw[0] + dw[1] + dw[2] + dw[3];
}

// ---------------------------------------------------------------------------
// Kernel 3: deterministic final reduction: mean(logZ) - mean(diag)
// 1024 threads so the 16384 g_diag loads are latency-overlapped.
// ---------------------------------------------------------------------------
__global__ void __launch_bounds__(1024) ContrastiveFinal(float* out) {
    __shared__ float red[1024];
    int t = threadIdx.x;
    float s = 0.f;
#pragma unroll
    for (int i = 0; i < 16; i++) s -= g_diag[t + (i << 10)];
    if (t < NCTA) s += g_partials[t];
    red[t] = s;
    __syncthreads();
#pragma unroll
    for (int k = 512; k; k >>= 1) {
        if (t < k) red[t] += red[t + k];
        __syncthreads();
    }
    if (t == 0) out[0] = red[0] / (float)NROW;
}

// ---------------------------------------------------------------------------
extern "C" void kernel_launch(void* const* d_in, const int* in_sizes, int n_in,
                              void* d_out, int out_size) {
    const float* O = (const float*)d_in[0];
    const float* T = (const float*)d_in[1];
    cudaFuncSetAttribute(ContrastiveMain,
                         cudaFuncAttributeMaxDynamicSharedMemorySize, SMEM_DYN);
    ContrastivePrep<<<2048, 256>>>(O, T);
    ContrastiveMain<<<NCTA, 512, SMEM_DYN>>>();
    ContrastiveFinal<<<1, 1024>>>((float*)d_out);
}

// round 11
// speedup vs baseline: 1.1967x; 1.0997x over previous
#include <cuda_runtime.h>
#include <cuda_bf16.h>
#include <cstdint>
#include <cstddef>

// ---------------------------------------------------------------------------
// ContrastiveLoss: loss = mean_i( log(sum_j exp(cos(o_i,t_j))) - cos(o_i,t_i) )
// B = 16384, D = 256, fp32 in, fp32 scalar out.
//
// bf16 mma.sync, 512 threads, warp tile 32x32 (4x4 grid), NT=128.
// NEW: 1024 jobs = 128 row-blocks x 8 column-chunks (16 tiles each) so all
// 148 SMs stay busy (6.92 waves, 98.9% quantization efficiency) instead of
// a single 128-CTA wave idling 20 SMs. Jobs emit raw per-row partial sums;
// the final kernel combines 8 partials/row -> logZ -> loss.
// Accumulator ping-pong epilogue (exp under tensor pipe) unchanged.
// ---------------------------------------------------------------------------

#define NROW   16384
#define DDIM   256
#define NCHUNK 8              // column chunks per row-block
#define TPJ    16             // tiles per job (128 / NCHUNK)
#define NJOBS  1024           // 128 row-blocks * NCHUNK

static __device__ __align__(16) __nv_bfloat16 g_obf[NROW * DDIM];
static __device__ __align__(16) __nv_bfloat16 g_tbf[NROW * DDIM];
static __device__ float g_diag[NROW];
static __device__ float g_psum[NJOBS * 128];   // per-job per-row partial sums

// SMEM layout: A 64KB resident, B0/B1 64KB each, reduction scratch.
#define OFF_A    0
#define OFF_B0   65536
#define OFF_B1   131072
#define OFF_RED  196608   // 4 x 128 floats
#define SMEM_DYN 198656

// ---------------------------------------------------------------------------
__device__ __forceinline__ uint32_t smem_u32(const void* p) {
    uint32_t a;
    asm("{ .reg .u64 t; cvta.to.shared.u64 t, %1; cvt.u32.u64 %0, t; }"
        : "=r"(a) : "l"(p));
    return a;
}
__device__ __forceinline__ void cp16(uint32_t dst, const void* src) {
    asm volatile("cp.async.cg.shared.global [%0], [%1], 16;" :: "r"(dst), "l"(src));
}
__device__ __forceinline__ void cp_commit() {
    asm volatile("cp.async.commit_group;" ::: "memory");
}
__device__ __forceinline__ void cp_wait0() {
    asm volatile("cp.async.wait_group 0;" ::: "memory");
}
__device__ __forceinline__ void ldm4(uint32_t* r, uint32_t addr) {
    asm volatile("ldmatrix.sync.aligned.m8n8.x4.shared.b16 {%0,%1,%2,%3}, [%4];"
                 : "=r"(r[0]), "=r"(r[1]), "=r"(r[2]), "=r"(r[3]) : "r"(addr));
}
__device__ __forceinline__ void mma16816(float* d, const uint32_t* a,
                                         uint32_t b0, uint32_t b1) {
    asm volatile(
        "mma.sync.aligned.m16n8k16.row.col.f32.bf16.bf16.f32 "
        "{%0,%1,%2,%3}, {%4,%5,%6,%7}, {%8,%9}, {%0,%1,%2,%3};"
        : "+f"(d[0]), "+f"(d[1]), "+f"(d[2]), "+f"(d[3])
        : "r"(a[0]), "r"(a[1]), "r"(a[2]), "r"(a[3]), "r"(b0), "r"(b1));
}

// Copy one 128x256 bf16 tile (64KB) into swizzled SMEM. 512 threads x 8 chunks.
__device__ __forceinline__ void tile_cp(const uint4* __restrict__ src,
                                        uint32_t dstbase, int tid) {
#pragma unroll
    for (int i = 0; i < 8; i++) {
        int c   = tid + (i << 9);
        int row = c >> 5, k16 = c & 31;
        cp16(dstbase + (row << 9) + ((k16 ^ (row & 7)) << 4), src + c);
    }
}

// ---------------------------------------------------------------------------
// Kernel 1: warp-per-row prep. Lane l owns elems [8l, 8l+8) of row r.
// ---------------------------------------------------------------------------
__global__ void __launch_bounds__(256) ContrastivePrep(
        const float* __restrict__ O, const float* __restrict__ T) {
    const int r    = blockIdx.x * 8 + (threadIdx.x >> 5);
    const int lane = threadIdx.x & 31;

    const float4* o4 = (const float4*)(O + (size_t)r * DDIM) + lane * 2;
    const float4* t4 = (const float4*)(T + (size_t)r * DDIM) + lane * 2;
    float4 a0 = o4[0], a1 = o4[1];
    float4 b0 = t4[0], b1 = t4[1];

    float so = a0.x*a0.x + a0.y*a0.y + a0.z*a0.z + a0.w*a0.w
             + a1.x*a1.x + a1.y*a1.y + a1.z*a1.z + a1.w*a1.w;
    float st = b0.x*b0.x + b0.y*b0.y + b0.z*b0.z + b0.w*b0.w
             + b1.x*b1.x + b1.y*b1.y + b1.z*b1.z + b1.w*b1.w;
#pragma unroll
    for (int s = 16; s; s >>= 1) {
        so += __shfl_xor_sync(0xffffffffu, so, s);
        st += __shfl_xor_sync(0xffffffffu, st, s);
    }
    const float io = rsqrtf(so), it = rsqrtf(st);

    __nv_bfloat162 oc[4], tc[4];
    oc[0] = __floats2bfloat162_rn(a0.x * io, a0.y * io);
    oc[1] = __floats2bfloat162_rn(a0.z * io, a0.w * io);
    oc[2] = __floats2bfloat162_rn(a1.x * io, a1.y * io);
    oc[3] = __floats2bfloat162_rn(a1.z * io, a1.w * io);
    tc[0] = __floats2bfloat162_rn(b0.x * it, b0.y * it);
    tc[1] = __floats2bfloat162_rn(b0.z * it, b0.w * it);
    tc[2] = __floats2bfloat162_rn(b1.x * it, b1.y * it);
    tc[3] = __floats2bfloat162_rn(b1.z * it, b1.w * it);
    ((uint4*)g_obf)[(size_t)r * 32 + lane] = *(uint4*)oc;
    ((uint4*)g_tbf)[(size_t)r * 32 + lane] = *(uint4*)tc;

    float dp = 0.f;
#pragma unroll
    for (int q = 0; q < 4; q++) {
        dp += __bfloat162float(oc[q].x) * __bfloat162float(tc[q].x)
            + __bfloat162float(oc[q].y) * __bfloat162float(tc[q].y);
    }
#pragma unroll
    for (int s = 16; s; s >>= 1) dp += __shfl_xor_sync(0xffffffffu, dp, s);
    if (lane == 0) g_diag[r] = dp;
}

// ---------------------------------------------------------------------------
// Kernel 2: fused GEMM + exp partial rowsums. 1024 CTAs x 512 threads.
// Job (i, c): row-block i (128 rows), column tiles [c*16, c*16+16).
// ---------------------------------------------------------------------------

// DC: accumulating set (this tile). DE: set being epilogued (previous tile).
#define TILE_BODY(DC, DE, BOFFS, EPI)                                         \
    do {                                                                      \
        const uint32_t bbase_ = sb + (BOFFS);                                 \
        _Pragma("unroll")                                                     \
        for (int ks = 0; ks < 16; ks++) {                                     \
            const uint32_t csel = (uint32_t)((((ks << 1) + lhi) ^ x7) << 4);  \
            uint32_t A2[2][4], Bm[2][4];                                      \
            _Pragma("unroll")                                                 \
            for (int mf = 0; mf < 2; mf++) ldm4(A2[mf], aoff[mf] + csel);     \
            _Pragma("unroll")                                                 \
            for (int p = 0; p < 2; p++)    ldm4(Bm[p], bbase_ + boff[p] + csel); \
            _Pragma("unroll")                                                 \
            for (int mf = 0; mf < 2; mf++)                                    \
                _Pragma("unroll")                                             \
                for (int p = 0; p < 2; p++) {                                 \
                    mma16816(DC[mf][2 * p],     A2[mf], Bm[p][0], Bm[p][2]);  \
                    mma16816(DC[mf][2 * p + 1], A2[mf], Bm[p][1], Bm[p][3]);  \
                }                                                             \
            if (EPI) {                                                        \
                _Pragma("unroll")                                             \
                for (int i = 0; i < 2; i++) {                                 \
                    const int e  = 2 * ks + i;                                \
                    const int mf = e >> 4, nf = (e >> 2) & 3, r = e & 3;      \
                    float v = DE[mf][nf][r];                                  \
                    DE[mf][nf][r] = 0.f;                                      \
                    sums[mf * 2 + (r >> 1)] += __expf(v);                     \
                }                                                             \
            }                                                                 \
        }                                                                     \
    } while (0)

__global__ void __launch_bounds__(512, 1) ContrastiveMain() {
    extern __shared__ char smem[];
    const uint32_t sb = smem_u32(smem);
    const int tid  = threadIdx.x;
    const int lane = tid & 31, w = tid >> 5;
    const int wm = w >> 2, wn = w & 3;            // 4 x 4 warp grid
    const int g  = lane >> 2;
    // c-major job order: first wave shares B tiles in L2.
    const int iblk = blockIdx.x & 127;            // row-block
    const int cchk = blockIdx.x >> 7;             // column chunk
    const int j0   = cchk * TPJ;                  // first column tile

    const int lrow = ((lane >> 3) & 1) * 8 + (lane & 7);
    const int lhi  = lane >> 4;
    const int x7   = lane & 7;

    uint32_t aoff[2], boff[2];
#pragma unroll
    for (int mf = 0; mf < 2; mf++)
        aoff[mf] = sb + OFF_A + (uint32_t)((wm * 32 + mf * 16 + lrow) << 9);
#pragma unroll
    for (int p = 0; p < 2; p++)
        boff[p] = (uint32_t)((wn * 32 + p * 16 + lrow) << 9);

    // Prologue: resident A + B(j0)
    tile_cp((const uint4*)g_obf + (size_t)iblk * 4096, sb + OFF_A, tid);
    tile_cp((const uint4*)g_tbf + (size_t)j0 * 4096, sb + OFF_B0, tid);
    cp_commit();
    cp_wait0();
    __syncthreads();

    float d0[2][4][4], d1[2][4][4];
#pragma unroll
    for (int mf = 0; mf < 2; mf++)
#pragma unroll
        for (int nf = 0; nf < 4; nf++)
#pragma unroll
            for (int r = 0; r < 4; r++) { d0[mf][nf][r] = 0.f; d1[mf][nf][r] = 0.f; }

    float sums[4];
#pragma unroll
    for (int s = 0; s < 4; s++) sums[s] = 0.f;

    // Tile j0 (set d0, no epilogue); prefetch B(j0+1)
    tile_cp((const uint4*)g_tbf + (size_t)(j0 + 1) * 4096, sb + OFF_B1, tid);
    cp_commit();
    TILE_BODY(d0, d1, OFF_B0, false);
    cp_wait0();
    __syncthreads();

    // Tiles j0+1 .. j0+14 in 7 pairs
#pragma unroll 1
    for (int jp = 0; jp < 7; jp++) {
        // tile j0+2jp+1 (set d1 from B1, epi d0); prefetch j0+2jp+2 -> B0
        tile_cp((const uint4*)g_tbf + (size_t)(j0 + 2 * jp + 2) * 4096,
                sb + OFF_B0, tid);
        cp_commit();
        TILE_BODY(d1, d0, OFF_B1, true);
        cp_wait0();
        __syncthreads();
        // tile j0+2jp+2 (set d0 from B0, epi d1); prefetch j0+2jp+3 -> B1
        tile_cp((const uint4*)g_tbf + (size_t)(j0 + 2 * jp + 3) * 4096,
                sb + OFF_B1, tid);
        cp_commit();
        TILE_BODY(d0, d1, OFF_B0, true);
        cp_wait0();
        __syncthreads();
    }

    // Tile j0+15 (set d1 from B1, epi d0), then tail epilogue of d1
    TILE_BODY(d1, d0, OFF_B1, true);
#pragma unroll
    for (int e = 0; e < 32; e++) {
        const int mf = e >> 4, nf = (e >> 2) & 3, r = e & 3;
        sums[mf * 2 + (r >> 1)] += __expf(d1[mf][nf][r]);
    }

    // ---- partial-sum reduction (deterministic); NO log here ----
#pragma unroll
    for (int s = 0; s < 4; s++) {
        sums[s] += __shfl_xor_sync(0xffffffffu, sums[s], 1);
        sums[s] += __shfl_xor_sync(0xffffffffu, sums[s], 2);
    }
    float* rp = (float*)(smem + OFF_RED);   // [4][128]: per wn column-block
    if ((lane & 3) == 0) {
#pragma unroll
        for (int s = 0; s < 4; s++) {
            int row = wm * 32 + (s >> 1) * 16 + (s & 1) * 8 + g;
            rp[wn * 128 + row] = sums[s];
        }
    }
    __syncthreads();
    if (tid < 128) {
        float srow = rp[tid] + rp[128 + tid] + rp[256 + tid] + rp[384 + tid];
        g_psum[(uint32_t)blockIdx.x * 128u + (uint32_t)tid] = srow;
    }
}

// ---------------------------------------------------------------------------
// Kernel 3: per-row combine of NCHUNK partials -> logZ -> loss (1 block).
// ---------------------------------------------------------------------------
__global__ void __launch_bounds__(1024) ContrastiveFinal(float* out) {
    __shared__ float red[1024];
    const int t = threadIdx.x;
    float acc = 0.f;
#pragma unroll
    for (int k = 0; k < 16; k++) {
        const int gr  = t + (k << 10);         // global row
        const int ib  = gr >> 7, row = gr & 127;
        float s = 0.f;
#pragma unroll
        for (int c = 0; c < NCHUNK; c++)
            s += g_psum[(uint32_t)(c * 128 + ib) * 128u + (uint32_t)row];
        acc += __logf(s) - g_diag[gr];
    }
    red[t] = acc;
    __syncthreads();
#pragma unroll
    for (int k = 512; k; k >>= 1) {
        if (t < k) red[t] += red[t + k];
        __syncthreads();
    }
    if (t == 0) out[0] = red[0] / (float)NROW;
}

// ---------------------------------------------------------------------------
extern "C" void kernel_launch(void* const* d_in, const int* in_sizes, int n_in,
                              void* d_out, int out_size) {
    const float* O = (const float*)d_in[0];
    const float* T = (const float*)d_in[1];
    cudaFuncSetAttribute(ContrastiveMain,
                         cudaFuncAttributeMaxDynamicSharedMemorySize, SMEM_DYN);
    ContrastivePrep<<<2048, 256>>>(O, T);
    ContrastiveMain<<<NJOBS, 512, SMEM_DYN>>>();
    ContrastiveFinal<<<1, 1024>>>((float*)d_out);
}

// round 12
// speedup vs baseline: 1.2166x; 1.0166x over previous
#include <cuda_runtime.h>
#include <cuda_bf16.h>
#include <cstdint>
#include <cstddef>

// ---------------------------------------------------------------------------
// ContrastiveLoss: loss = mean_i( log(sum_j exp(cos(o_i,t_j))) - cos(o_i,t_i) )
// B = 16384, D = 256, fp32 in, fp32 scalar out.
//
// bf16 mma.sync, 512 threads, warp tile 32x32 (4x4 grid), NT=128.
// Persistent grid: 148 CTAs (one per SM); each processes a contiguous
// i-major range of the 1024 jobs (128 row-blocks x 8 column-chunks,
// 16 tiles each). A range spans <=2 row-blocks, so the resident A tile is
// loaded once or twice per CTA instead of once per job. Jobs emit raw
// per-row partial sums; the final kernel combines 8/row -> logZ -> loss.
// Accumulator ping-pong epilogue (exp under tensor pipe) unchanged.
// ---------------------------------------------------------------------------

#define NROW   16384
#define DDIM   256
#define NCHUNK 8              // column chunks per row-block
#define TPJ    16             // tiles per job (128 / NCHUNK)
#define NJOBS  1024           // 128 row-blocks * NCHUNK
#define NSM    148

static __device__ __align__(16) __nv_bfloat16 g_obf[NROW * DDIM];
static __device__ __align__(16) __nv_bfloat16 g_tbf[NROW * DDIM];
static __device__ float g_diag[NROW];
static __device__ float g_psum[NJOBS * 128];   // [iblk*8 + cchk][row]

// SMEM layout: A 64KB resident, B0/B1 64KB each, reduction scratch.
#define OFF_A    0
#define OFF_B0   65536
#define OFF_B1   131072
#define OFF_RED  196608   // 4 x 128 floats
#define SMEM_DYN 198656

// ---------------------------------------------------------------------------
__device__ __forceinline__ uint32_t smem_u32(const void* p) {
    uint32_t a;
    asm("{ .reg .u64 t; cvta.to.shared.u64 t, %1; cvt.u32.u64 %0, t; }"
        : "=r"(a) : "l"(p));
    return a;
}
__device__ __forceinline__ void cp16(uint32_t dst, const void* src) {
    asm volatile("cp.async.cg.shared.global [%0], [%1], 16;" :: "r"(dst), "l"(src));
}
__device__ __forceinline__ void cp_commit() {
    asm volatile("cp.async.commit_group;" ::: "memory");
}
__device__ __forceinline__ void cp_wait0() {
    asm volatile("cp.async.wait_group 0;" ::: "memory");
}
__device__ __forceinline__ void ldm4(uint32_t* r, uint32_t addr) {
    asm volatile("ldmatrix.sync.aligned.m8n8.x4.shared.b16 {%0,%1,%2,%3}, [%4];"
                 : "=r"(r[0]), "=r"(r[1]), "=r"(r[2]), "=r"(r[3]) : "r"(addr));
}
__device__ __forceinline__ void mma16816(float* d, const uint32_t* a,
                                         uint32_t b0, uint32_t b1) {
    asm volatile(
        "mma.sync.aligned.m16n8k16.row.col.f32.bf16.bf16.f32 "
        "{%0,%1,%2,%3}, {%4,%5,%6,%7}, {%8,%9}, {%0,%1,%2,%3};"
        : "+f"(d[0]), "+f"(d[1]), "+f"(d[2]), "+f"(d[3])
        : "r"(a[0]), "r"(a[1]), "r"(a[2]), "r"(a[3]), "r"(b0), "r"(b1));
}

// Copy one 128x256 bf16 tile (64KB) into swizzled SMEM. 512 threads x 8 chunks.
__device__ __forceinline__ void tile_cp(const uint4* __restrict__ src,
                                        uint32_t dstbase, int tid) {
#pragma unroll
    for (int i = 0; i < 8; i++) {
        int c   = tid + (i << 9);
        int row = c >> 5, k16 = c & 31;
        cp16(dstbase + (row << 9) + ((k16 ^ (row & 7)) << 4), src + c);
    }
}

// ---------------------------------------------------------------------------
// Kernel 1: warp-per-row prep. Lane l owns elems [8l, 8l+8) of row r.
// ---------------------------------------------------------------------------
__global__ void __launch_bounds__(256) ContrastivePrep(
        const float* __restrict__ O, const float* __restrict__ T) {
    const int r    = blockIdx.x * 8 + (threadIdx.x >> 5);
    const int lane = threadIdx.x & 31;

    const float4* o4 = (const float4*)(O + (size_t)r * DDIM) + lane * 2;
    const float4* t4 = (const float4*)(T + (size_t)r * DDIM) + lane * 2;
    float4 a0 = o4[0], a1 = o4[1];
    float4 b0 = t4[0], b1 = t4[1];

    float so = a0.x*a0.x + a0.y*a0.y + a0.z*a0.z + a0.w*a0.w
             + a1.x*a1.x + a1.y*a1.y + a1.z*a1.z + a1.w*a1.w;
    float st = b0.x*b0.x + b0.y*b0.y + b0.z*b0.z + b0.w*b0.w
             + b1.x*b1.x + b1.y*b1.y + b1.z*b1.z + b1.w*b1.w;
#pragma unroll
    for (int s = 16; s; s >>= 1) {
        so += __shfl_xor_sync(0xffffffffu, so, s);
        st += __shfl_xor_sync(0xffffffffu, st, s);
    }
    const float io = rsqrtf(so), it = rsqrtf(st);

    __nv_bfloat162 oc[4], tc[4];
    oc[0] = __floats2bfloat162_rn(a0.x * io, a0.y * io);
    oc[1] = __floats2bfloat162_rn(a0.z * io, a0.w * io);
    oc[2] = __floats2bfloat162_rn(a1.x * io, a1.y * io);
    oc[3] = __floats2bfloat162_rn(a1.z * io, a1.w * io);
    tc[0] = __floats2bfloat162_rn(b0.x * it, b0.y * it);
    tc[1] = __floats2bfloat162_rn(b0.z * it, b0.w * it);
    tc[2] = __floats2bfloat162_rn(b1.x * it, b1.y * it);
    tc[3] = __floats2bfloat162_rn(b1.z * it, b1.w * it);
    ((uint4*)g_obf)[(size_t)r * 32 + lane] = *(uint4*)oc;
    ((uint4*)g_tbf)[(size_t)r * 32 + lane] = *(uint4*)tc;

    float dp = 0.f;
#pragma unroll
    for (int q = 0; q < 4; q++) {
        dp += __bfloat162float(oc[q].x) * __bfloat162float(tc[q].x)
            + __bfloat162float(oc[q].y) * __bfloat162float(tc[q].y);
    }
#pragma unroll
    for (int s = 16; s; s >>= 1) dp += __shfl_xor_sync(0xffffffffu, dp, s);
    if (lane == 0) g_diag[r] = dp;
}

// ---------------------------------------------------------------------------
// Kernel 2: persistent fused GEMM + exp partial rowsums. 148 CTAs x 512 thr.
// CTA c: jobs q in [c*1024/148, (c+1)*1024/148), i-major (iblk=q>>3, c=q&7).
// ---------------------------------------------------------------------------

// DC: accumulating set (this tile). DE: set being epilogued (previous tile).
#define TILE_BODY(DC, DE, BOFFS, EPI)                                         \
    do {                                                                      \
        const uint32_t bbase_ = sb + (BOFFS);                                 \
        _Pragma("unroll")                                                     \
        for (int ks = 0; ks < 16; ks++) {                                     \
            const uint32_t csel = (uint32_t)((((ks << 1) + lhi) ^ x7) << 4);  \
            uint32_t A2[2][4], Bm[2][4];                                      \
            _Pragma("unroll")                                                 \
            for (int mf = 0; mf < 2; mf++) ldm4(A2[mf], aoff[mf] + csel);     \
            _Pragma("unroll")                                                 \
            for (int p = 0; p < 2; p++)    ldm4(Bm[p], bbase_ + boff[p] + csel); \
            _Pragma("unroll")                                                 \
            for (int mf = 0; mf < 2; mf++)                                    \
                _Pragma("unroll")                                             \
                for (int p = 0; p < 2; p++) {                                 \
                    mma16816(DC[mf][2 * p],     A2[mf], Bm[p][0], Bm[p][2]);  \
                    mma16816(DC[mf][2 * p + 1], A2[mf], Bm[p][1], Bm[p][3]);  \
                }                                                             \
            if (EPI) {                                                        \
                _Pragma("unroll")                                             \
                for (int i = 0; i < 2; i++) {                                 \
                    const int e  = 2 * ks + i;                                \
                    const int mf = e >> 4, nf = (e >> 2) & 3, r = e & 3;      \
                    float v = DE[mf][nf][r];                                  \
                    DE[mf][nf][r] = 0.f;                                      \
                    sums[mf * 2 + (r >> 1)] += __expf(v);                     \
                }                                                             \
            }                                                                 \
        }                                                                     \
    } while (0)

__global__ void __launch_bounds__(512, 1) ContrastiveMain() {
    extern __shared__ char smem[];
    const uint32_t sb = smem_u32(smem);
    const int tid  = threadIdx.x;
    const int lane = tid & 31, w = tid >> 5;
    const int wm = w >> 2, wn = w & 3;            // 4 x 4 warp grid
    const int g  = lane >> 2;

    const int lrow = ((lane >> 3) & 1) * 8 + (lane & 7);
    const int lhi  = lane >> 4;
    const int x7   = lane & 7;

    uint32_t aoff[2], boff[2];
#pragma unroll
    for (int mf = 0; mf < 2; mf++)
        aoff[mf] = sb + OFF_A + (uint32_t)((wm * 32 + mf * 16 + lrow) << 9);
#pragma unroll
    for (int p = 0; p < 2; p++)
        boff[p] = (uint32_t)((wn * 32 + p * 16 + lrow) << 9);

    const int qbeg = (blockIdx.x * NJOBS) / NSM;
    const int qend = ((blockIdx.x + 1) * NJOBS) / NSM;

    float d0[2][4][4], d1[2][4][4];
#pragma unroll
    for (int mf = 0; mf < 2; mf++)
#pragma unroll
        for (int nf = 0; nf < 4; nf++)
#pragma unroll
            for (int r = 0; r < 4; r++) { d0[mf][nf][r] = 0.f; d1[mf][nf][r] = 0.f; }

    int cur_iblk = -1;

#pragma unroll 1
    for (int q = qbeg; q < qend; q++) {
        const int iblk = q >> 3;
        const int j0   = (q & 7) * TPJ;

        // Prologue: A (only when row-block changes) + B(j0)
        if (iblk != cur_iblk) {
            tile_cp((const uint4*)g_obf + (size_t)iblk * 4096, sb + OFF_A, tid);
            cur_iblk = iblk;
        }
        tile_cp((const uint4*)g_tbf + (size_t)j0 * 4096, sb + OFF_B0, tid);
        cp_commit();
        cp_wait0();
        __syncthreads();

        float sums[4];
#pragma unroll
        for (int s = 0; s < 4; s++) sums[s] = 0.f;

        // Tile j0 (set d0, no epilogue); prefetch B(j0+1)
        tile_cp((const uint4*)g_tbf + (size_t)(j0 + 1) * 4096, sb + OFF_B1, tid);
        cp_commit();
        TILE_BODY(d0, d1, OFF_B0, false);
        cp_wait0();
        __syncthreads();

        // Tiles j0+1 .. j0+14 in 7 pairs
#pragma unroll 1
        for (int jp = 0; jp < 7; jp++) {
            tile_cp((const uint4*)g_tbf + (size_t)(j0 + 2 * jp + 2) * 4096,
                    sb + OFF_B0, tid);
            cp_commit();
            TILE_BODY(d1, d0, OFF_B1, true);
            cp_wait0();
            __syncthreads();
            tile_cp((const uint4*)g_tbf + (size_t)(j0 + 2 * jp + 3) * 4096,
                    sb + OFF_B1, tid);
            cp_commit();
            TILE_BODY(d0, d1, OFF_B0, true);
            cp_wait0();
            __syncthreads();
        }

        // Tile j0+15 (set d1 from B1, epi d0), then tail epilogue of d1
        TILE_BODY(d1, d0, OFF_B1, true);
#pragma unroll
        for (int e = 0; e < 32; e++) {
            const int mf = e >> 4, nf = (e >> 2) & 3, r = e & 3;
            sums[mf * 2 + (r >> 1)] += __expf(d1[mf][nf][r]);
            d1[mf][nf][r] = 0.f;
        }

        // ---- partial-sum reduction (deterministic); NO log here ----
#pragma unroll
        for (int s = 0; s < 4; s++) {
            sums[s] += __shfl_xor_sync(0xffffffffu, sums[s], 1);
            sums[s] += __shfl_xor_sync(0xffffffffu, sums[s], 2);
        }
        float* rp = (float*)(smem + OFF_RED);   // [4][128]
        if ((lane & 3) == 0) {
#pragma unroll
            for (int s = 0; s < 4; s++) {
                int row = wm * 32 + (s >> 1) * 16 + (s & 1) * 8 + g;
                rp[wn * 128 + row] = sums[s];
            }
        }
        __syncthreads();
        if (tid < 128) {
            float srow = rp[tid] + rp[128 + tid] + rp[256 + tid] + rp[384 + tid];
            g_psum[(uint32_t)q * 128u + (uint32_t)tid] = srow;
        }
        __syncthreads();   // rp reused next job
    }
}

// ---------------------------------------------------------------------------
// Kernel 3: per-row combine of NCHUNK partials -> logZ -> loss (1 block).
// psum layout is i-major: job q = iblk*8 + cchk.
// ---------------------------------------------------------------------------
__global__ void __launch_bounds__(1024) ContrastiveFinal(float* out) {
    __shared__ float red[1024];
    const int t = threadIdx.x;
    float acc = 0.f;
#pragma unroll
    for (int k = 0; k < 16; k++) {
        const int gr  = t + (k << 10);         // global row
        const int ib  = gr >> 7, row = gr & 127;
        float s = 0.f;
#pragma unroll
        for (int c = 0; c < NCHUNK; c++)
            s += g_psum[(uint32_t)((ib << 3) + c) * 128u + (uint32_t)row];
        acc += __logf(s) - g_diag[gr];
    }
    red[t] = acc;
    __syncthreads();
#pragma unroll
    for (int k = 512; k; k >>= 1) {
        if (t < k) red[t] += red[t + k];
        __syncthreads();
    }
    if (t == 0) out[0] = red[0] / (float)NROW;
}

// ---------------------------------------------------------------------------
extern "C" void kernel_launch(void* const* d_in, const int* in_sizes, int n_in,
                              void* d_out, int out_size) {
    const float* O = (const float*)d_in[0];
    const float* T = (const float*)d_in[1];
    cudaFuncSetAttribute(ContrastiveMain,
                         cudaFuncAttributeMaxDynamicSharedMemorySize, SMEM_DYN);
    ContrastivePrep<<<2048, 256>>>(O, T);
    ContrastiveMain<<<NSM, 512, SMEM_DYN>>>();
    ContrastiveFinal<<<1, 1024>>>((float*)d_out);
}